// round 16
// baseline (speedup 1.0000x reference)
#include <cuda_runtime.h>
#include <math.h>
#include <stdint.h>

#define B_    4
#define T_    2048
#define C_    1024
#define H_    16
#define D_    64
#define WIN_  256

// Scratch (device globals; no runtime allocation allowed)
__device__ float g_q[B_*H_*T_*D_];
__device__ float g_k[B_*H_*T_*D_];
__device__ float g_v[B_*H_*T_*D_];
__device__ __align__(16) float g_att[B_*T_*C_];
// Pre-rounded (tf32-in-fp32-bits) operand copies
__device__ __align__(16) float g_xr[B_*T_*C_];
__device__ __align__(16) float g_wqkv[3*C_*C_];
__device__ __align__(16) float g_wproj[C_*C_];

__device__ __forceinline__ uint32_t f2tf32(float x) {
    uint32_t r;
    asm("cvt.rna.tf32.f32 %0, %1;" : "=r"(r) : "f"(x));
    return r;
}

__device__ __forceinline__ void mma_tf32_16x8x8(
    float* d, const uint32_t* a, const uint32_t* b)
{
    asm volatile(
        "mma.sync.aligned.m16n8k8.row.col.f32.tf32.tf32.f32 "
        "{%0,%1,%2,%3}, {%4,%5,%6,%7}, {%8,%9}, {%0,%1,%2,%3};"
        : "+f"(d[0]), "+f"(d[1]), "+f"(d[2]), "+f"(d[3])
        : "r"(a[0]), "r"(a[1]), "r"(a[2]), "r"(a[3]),
          "r"(b[0]), "r"(b[1]));
}

__device__ __forceinline__ uint32_t smem_u32(const void* p) {
    uint32_t a;
    asm("{ .reg .u64 t; cvta.to.shared.u64 t, %1; cvt.u32.u64 %0, t; }"
        : "=r"(a) : "l"(p));
    return a;
}

__device__ __forceinline__ void cp16(uint32_t s, const void* g) {
    asm volatile("cp.async.cg.shared.global [%0], [%1], 16;"
                 :: "r"(s), "l"(g));
}
#define CP_COMMIT() asm volatile("cp.async.commit_group;" ::: "memory")
#define CP_WAIT(n)  asm volatile("cp.async.wait_group %0;" :: "n"(n) : "memory")

// ---------------------------------------------------------------------------
// Merged prepass: round fp32 -> tf32 bits for x, qkv_w, proj_w in one launch.
// ---------------------------------------------------------------------------
#define N4_X  (B_*T_*C_/4)      // 2097152
#define N4_WQ (3*C_*C_/4)       // 786432
#define N4_WP (C_*C_/4)         // 262144

__global__ void round_all(const float4* __restrict__ x,
                          const float4* __restrict__ wq,
                          const float4* __restrict__ wp)
{
    const int total = N4_X + N4_WQ + N4_WP;
    for (int i = blockIdx.x * blockDim.x + threadIdx.x; i < total;
         i += gridDim.x * blockDim.x) {
        const float4* src;
        float4* dst;
        if (i < N4_X)              { src = x  + i;                 dst = (float4*)g_xr    + i; }
        else if (i < N4_X + N4_WQ) { src = wq + (i - N4_X);        dst = (float4*)g_wqkv  + (i - N4_X); }
        else                       { src = wp + (i - N4_X - N4_WQ); dst = (float4*)g_wproj + (i - N4_X - N4_WQ); }
        float4 v = *src;
        v.x = __uint_as_float(f2tf32(v.x));
        v.y = __uint_as_float(f2tf32(v.y));
        v.z = __uint_as_float(f2tf32(v.z));
        v.w = __uint_as_float(f2tf32(v.w));
        *dst = v;
    }
}

// ---------------------------------------------------------------------------
// tf32 GEMM, NT (R13 config — best measured). 128 threads, CTA tile
// 128x128x32, warp tile 64x64. 3-stage cp.async, ONE barrier per chunk
// (issue after barrier). Pre-rounded operands.
// MODE 1: A=g_xr, B=g_wqkv, scatter q/k/v PRE-ROUNDED to tf32 bits.
// MODE 2: A=g_att (tf32 bits), B=g_wproj, plain fp32 out.
// ---------------------------------------------------------------------------
#define KPAD 36
#define BUFW (2 * 128 * KPAD)
#define GSMEM_BYTES (3 * BUFW * 4)   // 110592 B

template<int MODE>
__global__ __launch_bounds__(128, 2) void gemm_cp(
    const float* __restrict__ bias,
    float* __restrict__ Cout,
    int M, int N, int K)
{
    extern __shared__ uint32_t sm[];
    const uint32_t sbase = smem_u32(sm);

    const float* __restrict__ A  = (MODE == 1) ? g_xr   : (const float*)g_att;
    const float* __restrict__ Bw = (MODE == 1) ? g_wqkv : g_wproj;

    const int tid  = threadIdx.x;
    const int w    = tid >> 5;
    const int lane = tid & 31;
    const int g    = lane >> 2;
    const int q    = lane & 3;
    const int wm   = w & 1;
    const int wn   = w >> 1;
    const int m0   = blockIdx.y * 128;
    const int n0   = blockIdx.x * 128;

    float acc[4][8][4];
    #pragma unroll
    for (int i = 0; i < 4; i++)
        #pragma unroll
        for (int j = 0; j < 8; j++)
            #pragma unroll
            for (int r = 0; r < 4; r++) acc[i][j][r] = 0.f;

    const int nch = K / 32;

    auto issue = [&](int cc) {
        const int k0 = cc * 32;
        const uint32_t as = sbase + (cc % 3) * BUFW * 4;
        const uint32_t bs = as + 128 * KPAD * 4;
        #pragma unroll
        for (int it = 0; it < 8; it++) {
            int f   = tid + it * 128;
            int row = f >> 3;
            int k4  = (f & 7) << 2;
            const uint32_t so = (uint32_t)(row * KPAD + k4) * 4;
            cp16(as + so, &A [(long)(m0 + row) * K + k0 + k4]);
            cp16(bs + so, &Bw[(long)(n0 + row) * K + k0 + k4]);
        }
        CP_COMMIT();
    };

    issue(0);
    issue(1);

    for (int c = 0; c < nch; c++) {
        if (c + 1 < nch) { CP_WAIT(1); } else { CP_WAIT(0); }
        __syncthreads();
        if (c + 2 < nch) issue(c + 2);

        const uint32_t* As = sm + (c % 3) * BUFW;
        const uint32_t* Bs = As + 128 * KPAD;

        #pragma unroll
        for (int kk = 0; kk < 4; kk++) {
            const int kb = kk * 8;
            uint32_t af[4][4], bf[8][2];
            #pragma unroll
            for (int im = 0; im < 4; im++) {
                const int mr = wm * 64 + im * 16 + g;
                af[im][0] = As[ mr      * KPAD + kb + q];
                af[im][1] = As[(mr + 8) * KPAD + kb + q];
                af[im][2] = As[ mr      * KPAD + kb + q + 4];
                af[im][3] = As[(mr + 8) * KPAD + kb + q + 4];
            }
            #pragma unroll
            for (int in = 0; in < 8; in++) {
                const int nc = wn * 64 + in * 8 + g;
                bf[in][0] = Bs[nc * KPAD + kb + q];
                bf[in][1] = Bs[nc * KPAD + kb + q + 4];
            }
            #pragma unroll
            for (int im = 0; im < 4; im++)
                #pragma unroll
                for (int in = 0; in < 8; in++)
                    mma_tf32_16x8x8(acc[im][in], af[im], bf[in]);
        }
    }

    // Epilogue
    #pragma unroll
    for (int im = 0; im < 4; im++) {
        #pragma unroll
        for (int in = 0; in < 8; in++) {
            const int mbase = m0 + wm * 64 + im * 16 + g;
            const int nbase = n0 + wn * 64 + in * 8 + q * 2;
            #pragma unroll
            for (int r = 0; r < 4; r++) {
                const int m = mbase + (r >> 1) * 8;
                const int n = nbase + (r & 1);
                float v = acc[im][in][r] + bias[n];
                if (MODE == 1) {
                    int s = n >> 10;
                    int h = (n >> 6) & 15;
                    int d = n & 63;
                    int b = m >> 11;
                    int t = m & 2047;
                    float* dst = (s == 0) ? g_q : (s == 1 ? g_k : g_v);
                    dst[(((long)(b * H_ + h)) * T_ + t) * D_ + d] =
                        __uint_as_float(f2tf32(v));
                } else {
                    Cout[(long)m * N + n] = v;
                }
            }
        }
    }
}

// ---------------------------------------------------------------------------
// Tensor-core windowed attention, CK2=64: softmax update once per 64 keys
// (halves shfl-reduce / o-rescale / m,l frequency vs 32-key chunks; mma
// totals identical). 2-stage cp.async, two barriers per chunk (same total
// barrier count as R13's one-per-32). p overwrites s in registers.
// Max key index = q0+127 <= 2047, so no bounds checks in staging.
// ---------------------------------------------------------------------------
#define QT  128
#define CK2 64
#define AST (2 * CK2 * 68)                 // words per stage (K+V) = 8704
#define ASMEM_BYTES (2 * AST * 4)          // 69632 B dynamic

__global__ __launch_bounds__(256, 2) void attn_mma_kernel()
{
    extern __shared__ uint32_t dsm[];
    __shared__ uint32_t p_s[8][16][68];    // 34816 B static

    const uint32_t sbase = smem_u32(dsm);
    const int tid  = threadIdx.x;
    const int w    = tid >> 5;
    const int lane = tid & 31;
    const int g    = lane >> 2;
    const int q    = lane & 3;
    const int q0   = blockIdx.x * QT;
    const int h    = blockIdx.y;
    const int b    = blockIdx.z;

    const long bh   = (long)(b * H_ + h);
    const float* Qp = g_q + bh * T_ * D_;
    const float* Kp = g_k + bh * T_ * D_;
    const float* Vp = g_v + bh * T_ * D_;

    const int qw  = q0 + w * 16;
    const int qg0 = qw + g;
    const int qg1 = qw + g + 8;

    const float SC = 0.18033688011f;   // 0.125 * log2(e)
    uint32_t aq[8][4];
    #pragma unroll
    for (int kk = 0; kk < 8; kk++) {
        aq[kk][0] = f2tf32(Qp[(long)qg0 * D_ + kk * 8 + q    ] * SC);
        aq[kk][1] = f2tf32(Qp[(long)qg1 * D_ + kk * 8 + q    ] * SC);
        aq[kk][2] = f2tf32(Qp[(long)qg0 * D_ + kk * 8 + q + 4] * SC);
        aq[kk][3] = f2tf32(Qp[(long)qg1 * D_ + kk * 8 + q + 4] * SC);
    }

    int lo_blk = q0 - (WIN_ - 1);
    if (lo_blk < 0) lo_blk = 0;
    lo_blk &= ~(CK2 - 1);
    const int nchunks = ((q0 + QT - 1) - lo_blk) / CK2 + 1;   // >= 2

    // stage chunk cc (keys [lo_blk+64cc, +63]) into stage cc%2
    auto issue = [&](int cc) {
        const int ks = lo_blk + cc * CK2;
        const uint32_t kb = sbase + (cc & 1) * AST * 4;
        #pragma unroll
        for (int it = 0; it < 8; it++) {
            int f   = tid + it * 256;        // 0..2047
            int mat = f >> 10;               // 0:K 1:V
            int idx = f & 1023;
            int row = idx >> 4;              // key 0..63
            int c4  = (idx & 15) << 2;       // dim quad
            const float* src = (mat ? Vp : Kp) + (long)(ks + row) * D_ + c4;
            cp16(kb + (uint32_t)(mat * (CK2 * 68) + row * 68 + c4) * 4, src);
        }
        CP_COMMIT();
    };

    float o[8][4];
    #pragma unroll
    for (int dt = 0; dt < 8; dt++)
        #pragma unroll
        for (int r = 0; r < 4; r++) o[dt][r] = 0.f;
    float m0r = -1e30f, m1r = -1e30f, l0 = 0.f, l1 = 0.f;

    issue(0);

    for (int c = 0; c < nchunks; c++) {
        if (c + 1 < nchunks) { issue(c + 1); CP_WAIT(1); } else { CP_WAIT(0); }
        __syncthreads();   // all threads' stage-c data visible

        const int ks = lo_blk + c * CK2;
        const bool active =
            !(ks > qw + 15 || ks + CK2 - 1 < qw - (WIN_ - 1));

        if (active) {
            const uint32_t* ks_ = dsm + (c & 1) * AST;
            const uint32_t* vs_ = ks_ + CK2 * 68;

            // S = Q*K^T : 8 n-tiles x 8 k-steps
            float s[8][4];
            #pragma unroll
            for (int nt = 0; nt < 8; nt++)
                #pragma unroll
                for (int r = 0; r < 4; r++) s[nt][r] = 0.f;
            #pragma unroll
            for (int kk = 0; kk < 8; kk++) {
                uint32_t bf[8][2];
                #pragma unroll
                for (int nt = 0; nt < 8; nt++) {
                    bf[nt][0] = ks_[(nt * 8 + g) * 68 + kk * 8 + q];
                    bf[nt][1] = ks_[(nt * 8 + g) * 68 + kk * 8 + q + 4];
                }
                #pragma unroll
                for (int nt = 0; nt < 8; nt++)
                    mma_tf32_16x8x8(s[nt], aq[kk], bf[nt]);
            }

            // Mask: valid iff 0 <= q - j < WIN
            #pragma unroll
            for (int nt = 0; nt < 8; nt++) {
                const int j0 = ks + nt * 8 + 2 * q;
                const int j1 = j0 + 1;
                s[nt][0] = ((unsigned)(qg0 - j0) < WIN_) ? s[nt][0] : -1e30f;
                s[nt][1] = ((unsigned)(qg0 - j1) < WIN_) ? s[nt][1] : -1e30f;
                s[nt][2] = ((unsigned)(qg1 - j0) < WIN_) ? s[nt][2] : -1e30f;
                s[nt][3] = ((unsigned)(qg1 - j1) < WIN_) ? s[nt][3] : -1e30f;
            }

            float cm0 = -1e30f, cm1 = -1e30f;
            #pragma unroll
            for (int nt = 0; nt < 8; nt++) {
                cm0 = fmaxf(cm0, fmaxf(s[nt][0], s[nt][1]));
                cm1 = fmaxf(cm1, fmaxf(s[nt][2], s[nt][3]));
            }
            cm0 = fmaxf(cm0, __shfl_xor_sync(0xffffffffu, cm0, 1));
            cm0 = fmaxf(cm0, __shfl_xor_sync(0xffffffffu, cm0, 2));
            cm1 = fmaxf(cm1, __shfl_xor_sync(0xffffffffu, cm1, 1));
            cm1 = fmaxf(cm1, __shfl_xor_sync(0xffffffffu, cm1, 2));

            const float m0n = fmaxf(m0r, cm0), m1n = fmaxf(m1r, cm1);
            const float c0  = exp2f(m0r - m0n), c1 = exp2f(m1r - m1n);

            // p overwrites s
            float ps0 = 0.f, ps1 = 0.f;
            #pragma unroll
            for (int nt = 0; nt < 8; nt++) {
                s[nt][0] = exp2f(s[nt][0] - m0n);
                s[nt][1] = exp2f(s[nt][1] - m0n);
                s[nt][2] = exp2f(s[nt][2] - m1n);
                s[nt][3] = exp2f(s[nt][3] - m1n);
                ps0 += s[nt][0] + s[nt][1];
                ps1 += s[nt][2] + s[nt][3];
            }
            ps0 += __shfl_xor_sync(0xffffffffu, ps0, 1);
            ps0 += __shfl_xor_sync(0xffffffffu, ps0, 2);
            ps1 += __shfl_xor_sync(0xffffffffu, ps1, 1);
            ps1 += __shfl_xor_sync(0xffffffffu, ps1, 2);

            l0 = l0 * c0 + ps0;  m0r = m0n;
            l1 = l1 * c1 + ps1;  m1r = m1n;
            #pragma unroll
            for (int dt = 0; dt < 8; dt++) {
                o[dt][0] *= c0;  o[dt][1] *= c0;
                o[dt][2] *= c1;  o[dt][3] *= c1;
            }

            // P -> per-warp smem (tf32 bits), C-layout
            #pragma unroll
            for (int nt = 0; nt < 8; nt++) {
                uint2 u0, u1;
                u0.x = f2tf32(s[nt][0]); u0.y = f2tf32(s[nt][1]);
                u1.x = f2tf32(s[nt][2]); u1.y = f2tf32(s[nt][3]);
                *(uint2*)&p_s[w][g    ][nt * 8 + 2 * q] = u0;
                *(uint2*)&p_s[w][g + 8][nt * 8 + 2 * q] = u1;
            }
            __syncwarp();

            // O += P * V : 8 k-steps (keys) x 8 dim-tiles
            #pragma unroll
            for (int kk = 0; kk < 8; kk++) {
                uint32_t ap[4];
                ap[0] = p_s[w][g    ][kk * 8 + q];
                ap[1] = p_s[w][g + 8][kk * 8 + q];
                ap[2] = p_s[w][g    ][kk * 8 + q + 4];
                ap[3] = p_s[w][g + 8][kk * 8 + q + 4];
                #pragma unroll
                for (int dt = 0; dt < 8; dt++) {
                    uint32_t bv[2];
                    bv[0] = vs_[(kk * 8 + q    ) * 68 + dt * 8 + g];
                    bv[1] = vs_[(kk * 8 + q + 4) * 68 + dt * 8 + g];
                    mma_tf32_16x8x8(o[dt], ap, bv);
                }
            }
            __syncwarp();
        }

        __syncthreads();   // all reads of stage c%2 done before next issue
    }

    // Epilogue: store pre-rounded tf32 bits (proj GEMM consumes directly)
    const float i0 = 1.f / l0, i1 = 1.f / l1;
    #pragma unroll
    for (int dt = 0; dt < 8; dt++) {
        const int d = dt * 8 + 2 * q;
        float2 o0, o1;
        o0.x = __uint_as_float(f2tf32(o[dt][0] * i0));
        o0.y = __uint_as_float(f2tf32(o[dt][1] * i0));
        o1.x = __uint_as_float(f2tf32(o[dt][2] * i1));
        o1.y = __uint_as_float(f2tf32(o[dt][3] * i1));
        *(float2*)&g_att[((long)(b * T_ + qg0)) * C_ + h * D_ + d] = o0;
        *(float2*)&g_att[((long)(b * T_ + qg1)) * C_ + h * D_ + d] = o1;
    }
}

// ---------------------------------------------------------------------------
// Launch. Inputs identified by element count (all distinct).
// ---------------------------------------------------------------------------
extern "C" void kernel_launch(void* const* d_in, const int* in_sizes, int n_in,
                              void* d_out, int out_size)
{
    const float* x      = 0;
    const float* qkv_w  = 0;
    const float* qkv_b  = 0;
    const float* proj_w = 0;
    const float* proj_b = 0;

    for (int i = 0; i < n_in; i++) {
        switch (in_sizes[i]) {
            case B_ * T_ * C_:  x      = (const float*)d_in[i]; break; // 8388608
            case T_ * T_:       /* attn_mask — unused */         break; // 4194304
            case 3 * C_ * C_:   qkv_w  = (const float*)d_in[i]; break; // 3145728
            case 3 * C_:        qkv_b  = (const float*)d_in[i]; break; // 3072
            case C_ * C_:       proj_w = (const float*)d_in[i]; break; // 1048576
            case C_:            proj_b = (const float*)d_in[i]; break; // 1024
        }
    }

    float* out = (float*)d_out;

    cudaFuncSetAttribute(gemm_cp<1>,
        cudaFuncAttributeMaxDynamicSharedMemorySize, GSMEM_BYTES);
    cudaFuncSetAttribute(gemm_cp<2>,
        cudaFuncAttributeMaxDynamicSharedMemorySize, GSMEM_BYTES);
    cudaFuncSetAttribute(attn_mma_kernel,
        cudaFuncAttributeMaxDynamicSharedMemorySize, ASMEM_BYTES);

    // Merged prepass: round x, qkv_w, proj_w to tf32 bits
    round_all<<<2048, 256>>>((const float4*)x, (const float4*)qkv_w,
                             (const float4*)proj_w);

    // QKV: g_xr [8192,1024] x g_wqkv [3072,1024]^T -> scatter q/k/v
    {
        dim3 grid(3 * C_ / 128, (B_ * T_) / 128);
        gemm_cp<1><<<grid, 128, GSMEM_BYTES>>>(qkv_b, nullptr,
                                               B_ * T_, 3 * C_, C_);
    }
    // Attention (tensor-core, 64-key chunks, 2-stage cp.async)
    {
        dim3 grid(T_ / QT, H_, B_);
        attn_mma_kernel<<<grid, 256, ASMEM_BYTES>>>();
    }
    // Proj: g_att [8192,1024] x g_wproj [1024,1024]^T -> out
    {
        dim3 grid(C_ / 128, (B_ * T_) / 128);
        gemm_cp<2><<<grid, 128, GSMEM_BYTES>>>(proj_b, out,
                                               B_ * T_, C_, C_);
    }
}

// round 17
// speedup vs baseline: 1.0481x; 1.0481x over previous
#include <cuda_runtime.h>
#include <math.h>
#include <stdint.h>

#define B_    4
#define T_    2048
#define C_    1024
#define H_    16
#define D_    64
#define WIN_  256

// Scratch (device globals; no runtime allocation allowed)
// q/k/v fused: [B, T, 3, H, D] == [M=8192, 3072] — the QKV GEMM's natural
// row-major output layout (epilogue needs no scatter/decode).
__device__ __align__(16) float g_qkv[B_*T_*3*C_];
__device__ __align__(16) float g_att[B_*T_*C_];
// Pre-rounded (tf32-in-fp32-bits) operand copies
__device__ __align__(16) float g_xr[B_*T_*C_];
__device__ __align__(16) float g_wqkv[3*C_*C_];
__device__ __align__(16) float g_wproj[C_*C_];

__device__ __forceinline__ uint32_t f2tf32(float x) {
    uint32_t r;
    asm("cvt.rna.tf32.f32 %0, %1;" : "=r"(r) : "f"(x));
    return r;
}
__device__ __forceinline__ float rtf(float x) {
    return __uint_as_float(f2tf32(x));
}

__device__ __forceinline__ void mma_tf32_16x8x8(
    float* d, const uint32_t* a, const uint32_t* b)
{
    asm volatile(
        "mma.sync.aligned.m16n8k8.row.col.f32.tf32.tf32.f32 "
        "{%0,%1,%2,%3}, {%4,%5,%6,%7}, {%8,%9}, {%0,%1,%2,%3};"
        : "+f"(d[0]), "+f"(d[1]), "+f"(d[2]), "+f"(d[3])
        : "r"(a[0]), "r"(a[1]), "r"(a[2]), "r"(a[3]),
          "r"(b[0]), "r"(b[1]));
}

__device__ __forceinline__ uint32_t smem_u32(const void* p) {
    uint32_t a;
    asm("{ .reg .u64 t; cvta.to.shared.u64 t, %1; cvt.u32.u64 %0, t; }"
        : "=r"(a) : "l"(p));
    return a;
}

__device__ __forceinline__ void cp16(uint32_t s, const void* g) {
    asm volatile("cp.async.cg.shared.global [%0], [%1], 16;"
                 :: "r"(s), "l"(g));
}
#define CP_COMMIT() asm volatile("cp.async.commit_group;" ::: "memory")
#define CP_WAIT(n)  asm volatile("cp.async.wait_group %0;" :: "n"(n) : "memory")

// ---------------------------------------------------------------------------
// Merged prepass: round fp32 -> tf32 bits for x, qkv_w, proj_w (one launch).
// ---------------------------------------------------------------------------
#define N4_X  (B_*T_*C_/4)
#define N4_WQ (3*C_*C_/4)
#define N4_WP (C_*C_/4)

__global__ void round_all(const float4* __restrict__ x,
                          const float4* __restrict__ wq,
                          const float4* __restrict__ wp)
{
    const int total = N4_X + N4_WQ + N4_WP;
    for (int i = blockIdx.x * blockDim.x + threadIdx.x; i < total;
         i += gridDim.x * blockDim.x) {
        const float4* src;
        float4* dst;
        if (i < N4_X)              { src = x  + i;                  dst = (float4*)g_xr    + i; }
        else if (i < N4_X + N4_WQ) { src = wq + (i - N4_X);         dst = (float4*)g_wqkv  + (i - N4_X); }
        else                       { src = wp + (i - N4_X - N4_WQ); dst = (float4*)g_wproj + (i - N4_X - N4_WQ); }
        float4 v = *src;
        v.x = rtf(v.x); v.y = rtf(v.y); v.z = rtf(v.z); v.w = rtf(v.w);
        *dst = v;
    }
}

// ---------------------------------------------------------------------------
// tf32 GEMM, NT (R13 config). 128 threads, CTA tile 128x128x32, warp tile
// 64x64. 3-stage cp.async, ONE barrier per chunk (issue after barrier).
// MODE 1: A=g_xr, B=g_wqkv -> g_qkv row-major, rounded (coalesced float2).
// MODE 2: A=g_att (tf32 bits), B=g_wproj -> plain fp32 out.
// ---------------------------------------------------------------------------
#define KPAD 36
#define BUFW (2 * 128 * KPAD)
#define GSMEM_BYTES (3 * BUFW * 4)   // 110592 B

template<int MODE>
__global__ __launch_bounds__(128, 2) void gemm_cp(
    const float* __restrict__ bias,
    float* __restrict__ Cout,
    int M, int N, int K)
{
    extern __shared__ uint32_t sm[];
    const uint32_t sbase = smem_u32(sm);

    const float* __restrict__ A  = (MODE == 1) ? g_xr   : (const float*)g_att;
    const float* __restrict__ Bw = (MODE == 1) ? g_wqkv : g_wproj;

    const int tid  = threadIdx.x;
    const int w    = tid >> 5;
    const int lane = tid & 31;
    const int g    = lane >> 2;
    const int q    = lane & 3;
    const int wm   = w & 1;
    const int wn   = w >> 1;
    const int m0   = blockIdx.y * 128;
    const int n0   = blockIdx.x * 128;

    float acc[4][8][4];
    #pragma unroll
    for (int i = 0; i < 4; i++)
        #pragma unroll
        for (int j = 0; j < 8; j++)
            #pragma unroll
            for (int r = 0; r < 4; r++) acc[i][j][r] = 0.f;

    const int nch = K / 32;

    auto issue = [&](int cc) {
        const int k0 = cc * 32;
        const uint32_t as = sbase + (cc % 3) * BUFW * 4;
        const uint32_t bs = as + 128 * KPAD * 4;
        #pragma unroll
        for (int it = 0; it < 8; it++) {
            int f   = tid + it * 128;
            int row = f >> 3;
            int k4  = (f & 7) << 2;
            const uint32_t so = (uint32_t)(row * KPAD + k4) * 4;
            cp16(as + so, &A [(long)(m0 + row) * K + k0 + k4]);
            cp16(bs + so, &Bw[(long)(n0 + row) * K + k0 + k4]);
        }
        CP_COMMIT();
    };

    issue(0);
    issue(1);

    for (int c = 0; c < nch; c++) {
        if (c + 1 < nch) { CP_WAIT(1); } else { CP_WAIT(0); }
        __syncthreads();
        if (c + 2 < nch) issue(c + 2);

        const uint32_t* As = sm + (c % 3) * BUFW;
        const uint32_t* Bs = As + 128 * KPAD;

        #pragma unroll
        for (int kk = 0; kk < 4; kk++) {
            const int kb = kk * 8;
            uint32_t af[4][4], bf[8][2];
            #pragma unroll
            for (int im = 0; im < 4; im++) {
                const int mr = wm * 64 + im * 16 + g;
                af[im][0] = As[ mr      * KPAD + kb + q];
                af[im][1] = As[(mr + 8) * KPAD + kb + q];
                af[im][2] = As[ mr      * KPAD + kb + q + 4];
                af[im][3] = As[(mr + 8) * KPAD + kb + q + 4];
            }
            #pragma unroll
            for (int in = 0; in < 8; in++) {
                const int nc = wn * 64 + in * 8 + g;
                bf[in][0] = Bs[nc * KPAD + kb + q];
                bf[in][1] = Bs[nc * KPAD + kb + q + 4];
            }
            #pragma unroll
            for (int im = 0; im < 4; im++)
                #pragma unroll
                for (int in = 0; in < 8; in++)
                    mma_tf32_16x8x8(acc[im][in], af[im], bf[in]);
        }
    }

    // Epilogue
    #pragma unroll
    for (int im = 0; im < 4; im++) {
        #pragma unroll
        for (int in = 0; in < 8; in++) {
            const int mb = m0 + wm * 64 + im * 16 + g;
            const int nb = n0 + wn * 64 + in * 8 + q * 2;
            if (MODE == 1) {
                // g_qkv row-major [m, 3072], rounded; coalesced float2
                const float b0 = bias[nb], b1 = bias[nb + 1];
                float2 w0, w1;
                w0.x = rtf(acc[im][in][0] + b0);
                w0.y = rtf(acc[im][in][1] + b1);
                w1.x = rtf(acc[im][in][2] + b0);
                w1.y = rtf(acc[im][in][3] + b1);
                *(float2*)&g_qkv[(long)mb * (3 * C_) + nb]       = w0;
                *(float2*)&g_qkv[(long)(mb + 8) * (3 * C_) + nb] = w1;
            } else {
                #pragma unroll
                for (int r = 0; r < 4; r++) {
                    const int m = mb + (r >> 1) * 8;
                    const int n = nb + (r & 1);
                    Cout[(long)m * N + n] = acc[im][in][r] + bias[n];
                }
            }
        }
    }
}

// ---------------------------------------------------------------------------
// Tensor-core windowed attention (R13: CK2=32, 3-stage cp.async, one
// barrier/chunk, exp2 softmax, p_s pad 36). Reads fused g_qkv layout:
// row t of q/k/v for (b,h) at g_qkv[(b*T+t)*3072 + s*1024 + h*64].
// Epilogue stores g_att rounded to tf32 bits for the proj GEMM.
// ---------------------------------------------------------------------------
#define QT  128
#define CK2 32
#define AST (2 * CK2 * 68)
#define ASMEM_BYTES (3 * AST * 4)          // 52224 B
#define QKVS (3 * C_)                      // 3072 row stride

__global__ __launch_bounds__(256, 2) void attn_mma_kernel()
{
    extern __shared__ uint32_t dsm[];
    __shared__ uint32_t p_s[8][16][36];

    const uint32_t sbase = smem_u32(dsm);
    const int tid  = threadIdx.x;
    const int w    = tid >> 5;
    const int lane = tid & 31;
    const int g    = lane >> 2;
    const int q    = lane & 3;
    const int q0   = blockIdx.x * QT;
    const int h    = blockIdx.y;
    const int b    = blockIdx.z;

    const float* Qp = g_qkv + (long)b * T_ * QKVS            + h * D_;
    const float* Kp = g_qkv + (long)b * T_ * QKVS + C_       + h * D_;
    const float* Vp = g_qkv + (long)b * T_ * QKVS + 2 * C_   + h * D_;

    const int qw  = q0 + w * 16;
    const int qg0 = qw + g;
    const int qg1 = qw + g + 8;

    const float SC = 0.18033688011f;   // 0.125 * log2(e)
    uint32_t aq[8][4];
    #pragma unroll
    for (int kk = 0; kk < 8; kk++) {
        aq[kk][0] = f2tf32(Qp[(long)qg0 * QKVS + kk * 8 + q    ] * SC);
        aq[kk][1] = f2tf32(Qp[(long)qg1 * QKVS + kk * 8 + q    ] * SC);
        aq[kk][2] = f2tf32(Qp[(long)qg0 * QKVS + kk * 8 + q + 4] * SC);
        aq[kk][3] = f2tf32(Qp[(long)qg1 * QKVS + kk * 8 + q + 4] * SC);
    }

    int lo_blk = q0 - (WIN_ - 1);
    if (lo_blk < 0) lo_blk = 0;
    lo_blk &= ~(CK2 - 1);
    const int nchunks = ((q0 + QT - 1) - lo_blk) / CK2 + 1;

    auto issue = [&](int cc) {
        const int ks = lo_blk + cc * CK2;
        const uint32_t kb = sbase + (cc % 3) * AST * 4;
        #pragma unroll
        for (int it = 0; it < 4; it++) {
            int f   = tid + it * 256;
            int mat = f >> 9;
            int idx = f & 511;
            int row = idx >> 4;
            int c4  = (idx & 15) << 2;
            const float* src = (mat ? Vp : Kp) + (long)(ks + row) * QKVS + c4;
            cp16(kb + (uint32_t)(mat * (CK2 * 68) + row * 68 + c4) * 4, src);
        }
        CP_COMMIT();
    };

    float o[8][4];
    #pragma unroll
    for (int dt = 0; dt < 8; dt++)
        #pragma unroll
        for (int r = 0; r < 4; r++) o[dt][r] = 0.f;
    float m0r = -1e30f, m1r = -1e30f, l0 = 0.f, l1 = 0.f;

    issue(0);
    issue(1);

    for (int c = 0; c < nchunks; c++) {
        if (c + 1 < nchunks) { CP_WAIT(1); } else { CP_WAIT(0); }
        __syncthreads();
        if (c + 2 < nchunks) issue(c + 2);

        const int ks = lo_blk + c * CK2;
        if (ks > qw + 15 || ks + CK2 - 1 < qw - (WIN_ - 1)) continue;

        const uint32_t* ks_ = dsm + (c % 3) * AST;
        const uint32_t* vs_ = ks_ + CK2 * 68;

        float s[4][4];
        #pragma unroll
        for (int nt = 0; nt < 4; nt++)
            #pragma unroll
            for (int r = 0; r < 4; r++) s[nt][r] = 0.f;
        #pragma unroll
        for (int kk = 0; kk < 8; kk++) {
            uint32_t bf[4][2];
            #pragma unroll
            for (int nt = 0; nt < 4; nt++) {
                bf[nt][0] = ks_[(nt * 8 + g) * 68 + kk * 8 + q];
                bf[nt][1] = ks_[(nt * 8 + g) * 68 + kk * 8 + q + 4];
            }
            #pragma unroll
            for (int nt = 0; nt < 4; nt++)
                mma_tf32_16x8x8(s[nt], aq[kk], bf[nt]);
        }

        #pragma unroll
        for (int nt = 0; nt < 4; nt++) {
            const int j0 = ks + nt * 8 + 2 * q;
            const int j1 = j0 + 1;
            s[nt][0] = ((unsigned)(qg0 - j0) < WIN_) ? s[nt][0] : -1e30f;
            s[nt][1] = ((unsigned)(qg0 - j1) < WIN_) ? s[nt][1] : -1e30f;
            s[nt][2] = ((unsigned)(qg1 - j0) < WIN_) ? s[nt][2] : -1e30f;
            s[nt][3] = ((unsigned)(qg1 - j1) < WIN_) ? s[nt][3] : -1e30f;
        }

        float cm0 = -1e30f, cm1 = -1e30f;
        #pragma unroll
        for (int nt = 0; nt < 4; nt++) {
            cm0 = fmaxf(cm0, fmaxf(s[nt][0], s[nt][1]));
            cm1 = fmaxf(cm1, fmaxf(s[nt][2], s[nt][3]));
        }
        cm0 = fmaxf(cm0, __shfl_xor_sync(0xffffffffu, cm0, 1));
        cm0 = fmaxf(cm0, __shfl_xor_sync(0xffffffffu, cm0, 2));
        cm1 = fmaxf(cm1, __shfl_xor_sync(0xffffffffu, cm1, 1));
        cm1 = fmaxf(cm1, __shfl_xor_sync(0xffffffffu, cm1, 2));

        const float m0n = fmaxf(m0r, cm0), m1n = fmaxf(m1r, cm1);
        const float c0  = exp2f(m0r - m0n), c1 = exp2f(m1r - m1n);

        float p[4][4];
        float ps0 = 0.f, ps1 = 0.f;
        #pragma unroll
        for (int nt = 0; nt < 4; nt++) {
            p[nt][0] = exp2f(s[nt][0] - m0n);
            p[nt][1] = exp2f(s[nt][1] - m0n);
            p[nt][2] = exp2f(s[nt][2] - m1n);
            p[nt][3] = exp2f(s[nt][3] - m1n);
            ps0 += p[nt][0] + p[nt][1];
            ps1 += p[nt][2] + p[nt][3];
        }
        ps0 += __shfl_xor_sync(0xffffffffu, ps0, 1);
        ps0 += __shfl_xor_sync(0xffffffffu, ps0, 2);
        ps1 += __shfl_xor_sync(0xffffffffu, ps1, 1);
        ps1 += __shfl_xor_sync(0xffffffffu, ps1, 2);

        l0 = l0 * c0 + ps0;  m0r = m0n;
        l1 = l1 * c1 + ps1;  m1r = m1n;
        #pragma unroll
        for (int dt = 0; dt < 8; dt++) {
            o[dt][0] *= c0;  o[dt][1] *= c0;
            o[dt][2] *= c1;  o[dt][3] *= c1;
        }

        #pragma unroll
        for (int nt = 0; nt < 4; nt++) {
            uint2 u0, u1;
            u0.x = f2tf32(p[nt][0]); u0.y = f2tf32(p[nt][1]);
            u1.x = f2tf32(p[nt][2]); u1.y = f2tf32(p[nt][3]);
            *(uint2*)&p_s[w][g    ][nt * 8 + 2 * q] = u0;
            *(uint2*)&p_s[w][g + 8][nt * 8 + 2 * q] = u1;
        }
        __syncwarp();

        #pragma unroll
        for (int kk = 0; kk < 4; kk++) {
            uint32_t ap[4];
            ap[0] = p_s[w][g    ][kk * 8 + q];
            ap[1] = p_s[w][g + 8][kk * 8 + q];
            ap[2] = p_s[w][g    ][kk * 8 + q + 4];
            ap[3] = p_s[w][g + 8][kk * 8 + q + 4];
            #pragma unroll
            for (int dt = 0; dt < 8; dt++) {
                uint32_t bv[2];
                bv[0] = vs_[(kk * 8 + q    ) * 68 + dt * 8 + g];
                bv[1] = vs_[(kk * 8 + q + 4) * 68 + dt * 8 + g];
                mma_tf32_16x8x8(o[dt], ap, bv);
            }
        }
        __syncwarp();
    }

    // Epilogue: store pre-rounded tf32 bits (proj GEMM consumes directly)
    const float i0 = 1.f / l0, i1 = 1.f / l1;
    #pragma unroll
    for (int dt = 0; dt < 8; dt++) {
        const int d = dt * 8 + 2 * q;
        float2 o0, o1;
        o0.x = rtf(o[dt][0] * i0);
        o0.y = rtf(o[dt][1] * i0);
        o1.x = rtf(o[dt][2] * i1);
        o1.y = rtf(o[dt][3] * i1);
        *(float2*)&g_att[((long)(b * T_ + qg0)) * C_ + h * D_ + d] = o0;
        *(float2*)&g_att[((long)(b * T_ + qg1)) * C_ + h * D_ + d] = o1;
    }
}

// ---------------------------------------------------------------------------
// Launch. Inputs identified by element count (all distinct).
// ---------------------------------------------------------------------------
extern "C" void kernel_launch(void* const* d_in, const int* in_sizes, int n_in,
                              void* d_out, int out_size)
{
    const float* x      = 0;
    const float* qkv_w  = 0;
    const float* qkv_b  = 0;
    const float* proj_w = 0;
    const float* proj_b = 0;

    for (int i = 0; i < n_in; i++) {
        switch (in_sizes[i]) {
            case B_ * T_ * C_:  x      = (const float*)d_in[i]; break; // 8388608
            case T_ * T_:       /* attn_mask — unused */         break; // 4194304
            case 3 * C_ * C_:   qkv_w  = (const float*)d_in[i]; break; // 3145728
            case 3 * C_:        qkv_b  = (const float*)d_in[i]; break; // 3072
            case C_ * C_:       proj_w = (const float*)d_in[i]; break; // 1048576
            case C_:            proj_b = (const float*)d_in[i]; break; // 1024
        }
    }

    float* out = (float*)d_out;

    cudaFuncSetAttribute(gemm_cp<1>,
        cudaFuncAttributeMaxDynamicSharedMemorySize, GSMEM_BYTES);
    cudaFuncSetAttribute(gemm_cp<2>,
        cudaFuncAttributeMaxDynamicSharedMemorySize, GSMEM_BYTES);
    cudaFuncSetAttribute(attn_mma_kernel,
        cudaFuncAttributeMaxDynamicSharedMemorySize, ASMEM_BYTES);

    // Merged prepass: round x, qkv_w, proj_w to tf32 bits
    round_all<<<2048, 256>>>((const float4*)x, (const float4*)qkv_w,
                             (const float4*)proj_w);

    // QKV: g_xr [8192,1024] x g_wqkv [3072,1024]^T -> g_qkv [8192,3072]
    {
        dim3 grid(3 * C_ / 128, (B_ * T_) / 128);
        gemm_cp<1><<<grid, 128, GSMEM_BYTES>>>(qkv_b, nullptr,
                                               B_ * T_, 3 * C_, C_);
    }
    // Attention (tensor-core, 3-stage cp.async)
    {
        dim3 grid(T_ / QT, H_, B_);
        attn_mma_kernel<<<grid, 256, ASMEM_BYTES>>>();
    }
    // Proj: g_att [8192,1024] x g_wproj [1024,1024]^T -> out
    {
        dim3 grid(C_ / 128, (B_ * T_) / 128);
        gemm_cp<2><<<grid, 128, GSMEM_BYTES>>>(proj_b, out,
                                               B_ * T_, C_, C_);
    }
}